// round 2
// baseline (speedup 1.0000x reference)
#include <cuda_runtime.h>
#include <math.h>

#define N_NODES 200000
#define N_EDGES 3200000

typedef unsigned long long u64;

// ---------------- static scratch ----------------
__device__ int    g_count [N_NODES];
__device__ int    g_rowptr[N_NODES];
__device__ int    g_cursor[N_NODES];
__device__ int    g_bsums [256];
__device__ float4 g_sedge [N_EDGES];     // {src(as float bits), kw0, kw1, pad}
__device__ float  g_h     [N_NODES * 32];
__device__ float  g_agg1  [N_NODES * 64];

// ---------------- packed f32x2 helpers ----------------
__device__ __forceinline__ u64 splat2(float x) {
    u64 r; unsigned xi = __float_as_uint(x);
    asm("mov.b64 %0, {%1, %1};" : "=l"(r) : "r"(xi));
    return r;
}
__device__ __forceinline__ void ffma2(u64& d, u64 a, u64 b) {
    asm("fma.rn.f32x2 %0, %1, %2, %0;" : "+l"(d) : "l"(a), "l"(b));
}

// ---------------- CSR build ----------------
__global__ void k_init() {
    int i = blockIdx.x * blockDim.x + threadIdx.x;
    if (i < N_NODES) g_count[i] = 0;
}

__global__ void k_hist(const int* __restrict__ dst) {
    int e = blockIdx.x * blockDim.x + threadIdx.x;
    if (e < N_EDGES) atomicAdd(&g_count[dst[e]], 1);
}

__global__ void k_scan1() {
    __shared__ int s[1024];
    int tid = threadIdx.x;
    int i = blockIdx.x * 1024 + tid;
    int v = (i < N_NODES) ? g_count[i] : 0;
    s[tid] = v;
    __syncthreads();
    for (int d = 1; d < 1024; d <<= 1) {
        int t = (tid >= d) ? s[tid - d] : 0;
        __syncthreads();
        s[tid] += t;
        __syncthreads();
    }
    if (i < N_NODES) g_rowptr[i] = s[tid] - v;
    if (tid == 1023) g_bsums[blockIdx.x] = s[1023];
}

__global__ void k_scan2(int nb) {
    __shared__ int s[256];
    int tid = threadIdx.x;
    s[tid] = (tid < nb) ? g_bsums[tid] : 0;
    __syncthreads();
    if (tid == 0) {
        int run = 0;
        for (int i = 0; i < nb; i++) { int v = s[i]; s[i] = run; run += v; }
    }
    __syncthreads();
    if (tid < nb) g_bsums[tid] = s[tid];
}

__global__ void k_scan3() {
    int i = blockIdx.x * blockDim.x + threadIdx.x;
    if (i < N_NODES) {
        int v = g_rowptr[i] + g_bsums[i >> 10];
        g_rowptr[i] = v;
        g_cursor[i] = v;
    }
}

__global__ void k_scatter(const int* __restrict__ src, const int* __restrict__ dst,
                          const float* __restrict__ kw) {
    int e = blockIdx.x * blockDim.x + threadIdx.x;
    if (e < N_EDGES) {
        int t = dst[e];
        int p = atomicAdd(&g_cursor[t], 1);
        float4 v;
        v.x = __int_as_float(src[e]);
        v.y = kw[e];
        v.z = kw[N_EDGES + e];
        v.w = 0.f;
        g_sedge[p] = v;
    }
}

// ---------------- fused conv0 + mlp0 + L2norm: warp per node ----------------
// aniso_conv(x) -> [16], @W0(16x32)+b0 -> [32], l2norm -> g_h[node*32 + lane]
__global__ void k_conv0(const float* __restrict__ x,
                        const float* __restrict__ W0, const float* __restrict__ b0) {
    __shared__ float W0s[512];
    __shared__ float b0s[32];
    int tid = threadIdx.x;
    W0s[tid] = W0[tid];
    W0s[tid + 256] = W0[tid + 256];
    if (tid < 32) b0s[tid] = b0[tid];
    __syncthreads();

    int warp = tid >> 5, lane = tid & 31;
    int node = blockIdx.x * 8 + warp;
    int f = lane & 7, sub = lane >> 3;
    int start = g_rowptr[node], end = start + g_count[node];
    float a0 = 0.f, a1 = 0.f;
    int e = start;
    for (; e + 4 <= end; e += 4) {
        float4 E = g_sedge[e + sub];
        int s = __float_as_int(E.x);
        float v = __ldg(&x[s * 8 + f]);
        a0 = fmaf(E.y, v, a0);
        a1 = fmaf(E.z, v, a1);
    }
    if (e + sub < end) {
        float4 E = g_sedge[e + sub];
        int s = __float_as_int(E.x);
        float v = __ldg(&x[s * 8 + f]);
        a0 = fmaf(E.y, v, a0);
        a1 = fmaf(E.z, v, a1);
    }
    // reduce across the 4 edge sub-lanes
    a0 += __shfl_xor_sync(0xffffffffu, a0, 8);
    a0 += __shfl_xor_sync(0xffffffffu, a0, 16);
    a1 += __shfl_xor_sync(0xffffffffu, a1, 8);
    a1 += __shfl_xor_sync(0xffffffffu, a1, 16);

    // agg[k] lives on lane k (k<8: a0, 8<=k<16: a1)
    float val = (lane & 8) ? a1 : a0;
    float acc = b0s[lane];
#pragma unroll
    for (int k = 0; k < 16; k++) {
        float ak = __shfl_sync(0xffffffffu, val, k);
        acc = fmaf(ak, W0s[k * 32 + lane], acc);
    }
    // L2 norm over the 32 lanes
    float ss = acc * acc;
#pragma unroll
    for (int o = 16; o; o >>= 1) ss += __shfl_xor_sync(0xffffffffu, ss, o);
    float sc = 1.f / fmaxf(sqrtf(ss), 1e-12f);
    g_h[node * 32 + lane] = acc * sc;
}

// ---------------- layer 1 conv: warp per node, lane = feature ----------------
__global__ void k_conv1() {
    int warp = threadIdx.x >> 5, lane = threadIdx.x & 31;
    int node = blockIdx.x * 8 + warp;
    int start = g_rowptr[node], end = start + g_count[node];
    float a0 = 0.f, a1 = 0.f;
    const float* __restrict__ h = g_h;
    int e = start;
    for (; e + 4 <= end; e += 4) {
        float4 E0 = g_sedge[e], E1 = g_sedge[e+1], E2 = g_sedge[e+2], E3 = g_sedge[e+3];
        float v0 = h[__float_as_int(E0.x) * 32 + lane];
        float v1 = h[__float_as_int(E1.x) * 32 + lane];
        float v2 = h[__float_as_int(E2.x) * 32 + lane];
        float v3 = h[__float_as_int(E3.x) * 32 + lane];
        a0 = fmaf(E0.y, v0, a0); a0 = fmaf(E1.y, v1, a0);
        a0 = fmaf(E2.y, v2, a0); a0 = fmaf(E3.y, v3, a0);
        a1 = fmaf(E0.z, v0, a1); a1 = fmaf(E1.z, v1, a1);
        a1 = fmaf(E2.z, v2, a1); a1 = fmaf(E3.z, v3, a1);
    }
    for (; e < end; ++e) {
        float4 E = g_sedge[e];
        float v = h[__float_as_int(E.x) * 32 + lane];
        a0 = fmaf(E.y, v, a0);
        a1 = fmaf(E.z, v, a1);
    }
    g_agg1[node*64 + lane]      = a0;
    g_agg1[node*64 + 32 + lane] = a1;
}

// ---------------- layer 1 MLP (64 -> relu 128 -> 64) + L2 norm ----------------
// smem layout (floats):
#define SM_W1 0                      // 8192
#define SM_W2 8192                   // 8192
#define SM_A  16384                  // 64 rows x stride 129 = 8256
#define SM_B1 (16384 + 8256)         // 128
#define SM_B2 (SM_B1 + 128)          // 64
#define SM_TOTAL (SM_B2 + 64)
// z-staging after mm1 reuses the dead W1 region (pairs 0..31) and A region (32..63)

__global__ void __launch_bounds__(128, 2)
k_mlp1(const float* __restrict__ W1, const float* __restrict__ b1,
       const float* __restrict__ W2, const float* __restrict__ b2,
       float* __restrict__ out) {
    extern __shared__ float sm[];
    int tid = threadIdx.x;
    for (int i = tid; i < 8192; i += 128) {
        sm[SM_W1 + i] = W1[i];
        sm[SM_W2 + i] = W2[i];
    }
    sm[SM_B1 + tid] = b1[tid];
    if (tid < 64) sm[SM_B2 + tid] = b2[tid];

    int base = blockIdx.x * 128;
    // load A transposed: A[k][node_local], stride 129 kills STS bank conflicts
    for (int idx = tid; idx < 8192; idx += 128) {
        int g = base * 64 + idx;
        float v = (g < N_NODES * 64) ? g_agg1[g] : 0.f;
        sm[SM_A + (idx & 63) * 129 + (idx >> 6)] = v;
    }
    __syncthreads();

    // mm1: z[128] = a[64] @ W1 + b1   (64 packed f32x2 accumulators)
    u64 acc[64];
    const u64* b1v = (const u64*)(sm + SM_B1);
#pragma unroll
    for (int p = 0; p < 64; p++) acc[p] = b1v[p];
    const float* As = sm + SM_A;
#pragma unroll 2
    for (int k = 0; k < 64; k++) {
        u64 ak2 = splat2(As[k * 129 + tid]);
        const ulonglong2* w = (const ulonglong2*)(sm + SM_W1 + k * 128);
#pragma unroll
        for (int q = 0; q < 32; q++) {
            ulonglong2 wv = w[q];
            ffma2(acc[2*q],   ak2, wv.x);
            ffma2(acc[2*q+1], ak2, wv.y);
        }
    }

    // stage relu(z) into dead smem (W1 region + A region); frees registers for mm2
    __syncthreads();
    u64* Zlo = (u64*)(sm + SM_W1);
    u64* Zhi = (u64*)(sm + SM_A);
#pragma unroll
    for (int p = 0; p < 32; p++) {
        float lo = fmaxf(__uint_as_float((unsigned)acc[p]), 0.f);
        float hi = fmaxf(__uint_as_float((unsigned)(acc[p] >> 32)), 0.f);
        Zlo[p * 128 + tid] = ((u64)__float_as_uint(hi) << 32) | (u64)__float_as_uint(lo);
    }
#pragma unroll
    for (int p = 0; p < 32; p++) {
        float lo = fmaxf(__uint_as_float((unsigned)acc[32 + p]), 0.f);
        float hi = fmaxf(__uint_as_float((unsigned)(acc[32 + p] >> 32)), 0.f);
        Zhi[p * 128 + tid] = ((u64)__float_as_uint(hi) << 32) | (u64)__float_as_uint(lo);
    }
    __syncthreads();

    // mm2: o[64] = z[128] @ W2 + b2
    u64 outp[32];
    const u64* b2v = (const u64*)(sm + SM_B2);
#pragma unroll
    for (int q = 0; q < 32; q++) outp[q] = b2v[q];

#pragma unroll 4
    for (int p = 0; p < 32; p++) {           // k = 2p, 2p+1
        u64 z2 = Zlo[p * 128 + tid];
        u64 zl = splat2(__uint_as_float((unsigned)z2));
        u64 zh = splat2(__uint_as_float((unsigned)(z2 >> 32)));
        const ulonglong2* r0 = (const ulonglong2*)(sm + SM_W2 + (2*p)     * 64);
        const ulonglong2* r1 = (const ulonglong2*)(sm + SM_W2 + (2*p + 1) * 64);
#pragma unroll
        for (int q = 0; q < 16; q++) {
            ulonglong2 w0 = r0[q];
            ffma2(outp[2*q],   zl, w0.x);
            ffma2(outp[2*q+1], zl, w0.y);
        }
#pragma unroll
        for (int q = 0; q < 16; q++) {
            ulonglong2 w1 = r1[q];
            ffma2(outp[2*q],   zh, w1.x);
            ffma2(outp[2*q+1], zh, w1.y);
        }
    }
#pragma unroll 4
    for (int p = 0; p < 32; p++) {           // k = 64+2p, 64+2p+1
        u64 z2 = Zhi[p * 128 + tid];
        u64 zl = splat2(__uint_as_float((unsigned)z2));
        u64 zh = splat2(__uint_as_float((unsigned)(z2 >> 32)));
        const ulonglong2* r0 = (const ulonglong2*)(sm + SM_W2 + (64 + 2*p)     * 64);
        const ulonglong2* r1 = (const ulonglong2*)(sm + SM_W2 + (64 + 2*p + 1) * 64);
#pragma unroll
        for (int q = 0; q < 16; q++) {
            ulonglong2 w0 = r0[q];
            ffma2(outp[2*q],   zl, w0.x);
            ffma2(outp[2*q+1], zl, w0.y);
        }
#pragma unroll
        for (int q = 0; q < 16; q++) {
            ulonglong2 w1 = r1[q];
            ffma2(outp[2*q],   zh, w1.x);
            ffma2(outp[2*q+1], zh, w1.y);
        }
    }

    // L2 normalize + store
    float o[64];
    float ss = 0.f;
#pragma unroll
    for (int q = 0; q < 32; q++) {
        float lo = __uint_as_float((unsigned)outp[q]);
        float hi = __uint_as_float((unsigned)(outp[q] >> 32));
        o[2*q] = lo; o[2*q+1] = hi;
        ss = fmaf(lo, lo, ss);
        ss = fmaf(hi, hi, ss);
    }
    int node = base + tid;
    if (node < N_NODES) {
        float sc = 1.f / fmaxf(sqrtf(ss), 1e-12f);
        float4* op = (float4*)(out + node * 64);
#pragma unroll
        for (int q = 0; q < 16; q++) {
            float4 v;
            v.x = o[4*q] * sc;   v.y = o[4*q+1] * sc;
            v.z = o[4*q+2] * sc; v.w = o[4*q+3] * sc;
            op[q] = v;
        }
    }
}

// ---------------- launch ----------------
extern "C" void kernel_launch(void* const* d_in, const int* in_sizes, int n_in,
                              void* d_out, int out_size) {
    const float* x  = (const float*)d_in[0];
    const int*   ei = (const int*)  d_in[1];
    const float* kw = (const float*)d_in[2];
    const float* W0 = (const float*)d_in[3];
    const float* b0 = (const float*)d_in[4];
    const float* W1 = (const float*)d_in[5];
    const float* b1 = (const float*)d_in[6];
    const float* W2 = (const float*)d_in[7];
    const float* b2 = (const float*)d_in[8];
    float* out = (float*)d_out;
    const int* src = ei;
    const int* dst = ei + N_EDGES;

    cudaFuncSetAttribute(k_mlp1, cudaFuncAttributeMaxDynamicSharedMemorySize,
                         SM_TOTAL * (int)sizeof(float));

    k_init   <<<(N_NODES + 255) / 256, 256>>>();
    k_hist   <<<(N_EDGES + 255) / 256, 256>>>(dst);
    k_scan1  <<<(N_NODES + 1023) / 1024, 1024>>>();
    k_scan2  <<<1, 256>>>((N_NODES + 1023) / 1024);
    k_scan3  <<<(N_NODES + 255) / 256, 256>>>();
    k_scatter<<<(N_EDGES + 255) / 256, 256>>>(src, dst, kw);
    k_conv0  <<<N_NODES / 8, 256>>>(x, W0, b0);
    k_conv1  <<<N_NODES / 8, 256>>>();
    k_mlp1   <<<(N_NODES + 127) / 128, 128, SM_TOTAL * (int)sizeof(float)>>>(W1, b1, W2, b2, out);
}

// round 3
// speedup vs baseline: 1.0444x; 1.0444x over previous
#include <cuda_runtime.h>
#include <math.h>

#define N_NODES 200000
#define N_EDGES 3200000

typedef unsigned long long u64;

// ---------------- static scratch ----------------
__device__ int    g_count [N_NODES];
__device__ int    g_rowptr[N_NODES];
__device__ int    g_cursor[N_NODES];
__device__ int    g_bsums [256];
__device__ float4 g_sedge [N_EDGES];     // {src(bits), kw0, kw1, pad}
__device__ float  g_h     [N_NODES * 32];
__device__ float  g_agg1  [N_NODES * 64];

// ---------------- packed f32x2 helpers ----------------
__device__ __forceinline__ u64 splat2(float x) {
    u64 r; unsigned xi = __float_as_uint(x);
    asm("mov.b64 %0, {%1, %1};" : "=l"(r) : "r"(xi));
    return r;
}
__device__ __forceinline__ void ffma2(u64& d, u64 a, u64 b) {
    asm("fma.rn.f32x2 %0, %1, %2, %0;" : "+l"(d) : "l"(a), "l"(b));
}
__device__ __forceinline__ u64 add2(u64 a, u64 b) {
    u64 r; asm("add.rn.f32x2 %0, %1, %2;" : "=l"(r) : "l"(a), "l"(b));
    return r;
}

// ---------------- CSR build ----------------
__global__ void k_init() {
    int i = blockIdx.x * blockDim.x + threadIdx.x;
    if (i < N_NODES) g_count[i] = 0;
}

__global__ void k_hist(const int* __restrict__ dst) {
    int e = blockIdx.x * blockDim.x + threadIdx.x;
    if (e < N_EDGES) atomicAdd(&g_count[dst[e]], 1);
}

// block-local exclusive scan over 1024 nodes (shuffle-based), block totals to g_bsums
__global__ void k_scan1() {
    __shared__ int wsum[32];
    int tid = threadIdx.x;
    int i = blockIdx.x * 1024 + tid;
    int v = (i < N_NODES) ? g_count[i] : 0;
    int s = v;
#pragma unroll
    for (int o = 1; o < 32; o <<= 1) {
        int t = __shfl_up_sync(0xffffffffu, s, o);
        if ((tid & 31) >= o) s += t;
    }
    if ((tid & 31) == 31) wsum[tid >> 5] = s;
    __syncthreads();
    if (tid < 32) {
        int w = wsum[tid];
        int ws = w;
#pragma unroll
        for (int o = 1; o < 32; o <<= 1) {
            int t = __shfl_up_sync(0xffffffffu, ws, o);
            if (tid >= o) ws += t;
        }
        wsum[tid] = ws - w;   // exclusive warp offset
    }
    __syncthreads();
    int excl = s - v + wsum[tid >> 5];
    if (i < N_NODES) g_rowptr[i] = excl;
    if (tid == 1023) g_bsums[blockIdx.x] = excl + v;
}

// each 256-node block adds the prefix of its 1024-group (sum of earlier block totals)
__global__ void k_offsets() {
    __shared__ int soff;
    int g = blockIdx.x >> 2;
    int tid = threadIdx.x;
    if (tid < 32) {
        int acc = 0;
        for (int j = tid; j < g; j += 32) acc += g_bsums[j];
#pragma unroll
        for (int o = 16; o; o >>= 1) acc += __shfl_xor_sync(0xffffffffu, acc, o);
        if (tid == 0) soff = acc;
    }
    __syncthreads();
    int i = blockIdx.x * 256 + tid;
    if (i < N_NODES) {
        int v = g_rowptr[i] + soff;
        g_rowptr[i] = v;
        g_cursor[i] = v;
    }
}

__global__ void k_scatter(const int* __restrict__ src, const int* __restrict__ dst,
                          const float* __restrict__ kw) {
    int e = blockIdx.x * blockDim.x + threadIdx.x;
    if (e < N_EDGES) {
        int t = dst[e];
        int p = atomicAdd(&g_cursor[t], 1);
        float4 v;
        v.x = __int_as_float(src[e]);
        v.y = kw[e];
        v.z = kw[N_EDGES + e];
        v.w = 0.f;
        g_sedge[p] = v;
    }
}

// ---------------- fused conv0 + mlp0 + L2norm: warp per node ----------------
__global__ void k_conv0(const float* __restrict__ x,
                        const float* __restrict__ W0, const float* __restrict__ b0) {
    __shared__ float W0s[512];
    __shared__ float b0s[32];
    int tid = threadIdx.x;
    W0s[tid] = W0[tid];
    W0s[tid + 256] = W0[tid + 256];
    if (tid < 32) b0s[tid] = b0[tid];
    __syncthreads();

    int warp = tid >> 5, lane = tid & 31;
    int node = blockIdx.x * 8 + warp;
    int f = lane & 7, sub = lane >> 3;
    int start = g_rowptr[node], end = start + g_count[node];
    float a0 = 0.f, a1 = 0.f;
    int e = start;
    for (; e + 4 <= end; e += 4) {
        float4 E = g_sedge[e + sub];
        int s = __float_as_int(E.x);
        float v = __ldg(&x[s * 8 + f]);
        a0 = fmaf(E.y, v, a0);
        a1 = fmaf(E.z, v, a1);
    }
    if (e + sub < end) {
        float4 E = g_sedge[e + sub];
        int s = __float_as_int(E.x);
        float v = __ldg(&x[s * 8 + f]);
        a0 = fmaf(E.y, v, a0);
        a1 = fmaf(E.z, v, a1);
    }
    a0 += __shfl_xor_sync(0xffffffffu, a0, 8);
    a0 += __shfl_xor_sync(0xffffffffu, a0, 16);
    a1 += __shfl_xor_sync(0xffffffffu, a1, 8);
    a1 += __shfl_xor_sync(0xffffffffu, a1, 16);

    float val = (lane & 8) ? a1 : a0;   // agg[k] on lane k, k<16
    float acc = b0s[lane];
#pragma unroll
    for (int k = 0; k < 16; k++) {
        float ak = __shfl_sync(0xffffffffu, val, k);
        acc = fmaf(ak, W0s[k * 32 + lane], acc);
    }
    float ss = acc * acc;
#pragma unroll
    for (int o = 16; o; o >>= 1) ss += __shfl_xor_sync(0xffffffffu, ss, o);
    float sc = 1.f / fmaxf(sqrtf(ss), 1e-12f);
    g_h[node * 32 + lane] = acc * sc;
}

// ---------------- layer 1 conv: warp per node, lane = feature ----------------
__global__ void k_conv1() {
    int warp = threadIdx.x >> 5, lane = threadIdx.x & 31;
    int node = blockIdx.x * 8 + warp;
    int start = g_rowptr[node], end = start + g_count[node];
    float a0 = 0.f, a1 = 0.f;
    const float* __restrict__ h = g_h;
    int e = start;
    for (; e + 4 <= end; e += 4) {
        float4 E0 = g_sedge[e], E1 = g_sedge[e+1], E2 = g_sedge[e+2], E3 = g_sedge[e+3];
        float v0 = h[__float_as_int(E0.x) * 32 + lane];
        float v1 = h[__float_as_int(E1.x) * 32 + lane];
        float v2 = h[__float_as_int(E2.x) * 32 + lane];
        float v3 = h[__float_as_int(E3.x) * 32 + lane];
        a0 = fmaf(E0.y, v0, a0); a0 = fmaf(E1.y, v1, a0);
        a0 = fmaf(E2.y, v2, a0); a0 = fmaf(E3.y, v3, a0);
        a1 = fmaf(E0.z, v0, a1); a1 = fmaf(E1.z, v1, a1);
        a1 = fmaf(E2.z, v2, a1); a1 = fmaf(E3.z, v3, a1);
    }
    for (; e < end; ++e) {
        float4 E = g_sedge[e];
        float v = h[__float_as_int(E.x) * 32 + lane];
        a0 = fmaf(E.y, v, a0);
        a1 = fmaf(E.z, v, a1);
    }
    g_agg1[node*64 + lane]      = a0;
    g_agg1[node*64 + 32 + lane] = a1;
}

// ---------------- layer 1 MLP: 2 threads per node (half-split), no spills ----------------
// smem (floats): W1 [0,8192) | A [8192,16448) 64x129 | W2 [16448,24640) | b1 128 | b2 64
#define SM_W1 0
#define SM_A  8192
#define SM_W2 16448
#define SM_B1 24640
#define SM_B2 24768
#define SM_TOTAL 24832
// partial-o exchange reuses W1 region (dead after mm1): 32 u64 x 128 nodes = 32KB

__global__ void __launch_bounds__(256, 1)
k_mlp1(const float* __restrict__ W1, const float* __restrict__ b1,
       const float* __restrict__ W2, const float* __restrict__ b2,
       float* __restrict__ out) {
    extern __shared__ float sm[];
    int tid = threadIdx.x;
    for (int i = tid; i < 8192; i += 256) {
        sm[SM_W1 + i] = W1[i];
        sm[SM_W2 + i] = W2[i];
    }
    if (tid < 128) sm[SM_B1 + tid] = b1[tid];
    if (tid < 64)  sm[SM_B2 + tid] = b2[tid];

    int base = blockIdx.x * 128;
    // stage A transposed: A[k][node_local], stride 129
    for (int idx = tid; idx < 8192; idx += 256) {
        int g = base * 64 + idx;
        float v = (g < N_NODES * 64) ? g_agg1[g] : 0.f;
        sm[SM_A + (idx & 63) * 129 + (idx >> 6)] = v;
    }
    __syncthreads();

    int node = tid & 127, half = tid >> 7;

    // mm1: z[half*64 .. +64) for own node  (32 packed pairs)
    u64 acc[32];
    const u64* b1v = (const u64*)(sm + SM_B1 + half * 64);
#pragma unroll
    for (int p = 0; p < 32; p++) acc[p] = b1v[p];
    const float* As = sm + SM_A;
    const float* W1h = sm + SM_W1 + half * 64;
#pragma unroll 2
    for (int k = 0; k < 64; k++) {
        u64 ak2 = splat2(As[k * 129 + node]);
        const ulonglong2* w = (const ulonglong2*)(W1h + k * 128);
#pragma unroll
        for (int q = 0; q < 16; q++) {
            ulonglong2 wv = w[q];
            ffma2(acc[2*q],   ak2, wv.x);
            ffma2(acc[2*q+1], ak2, wv.y);
        }
    }
    // relu in registers
#pragma unroll
    for (int p = 0; p < 32; p++) {
        float lo = fmaxf(__uint_as_float((unsigned)acc[p]), 0.f);
        float hi = fmaxf(__uint_as_float((unsigned)(acc[p] >> 32)), 0.f);
        acc[p] = ((u64)__float_as_uint(hi) << 32) | (u64)__float_as_uint(lo);
    }
    __syncthreads();   // all threads done reading W1 (its region becomes the exchange buffer)

    // mm2: partial o[64] over k in [half*64, half*64+64) — inputs are this thread's own z
    u64 outp[32];
    if (half == 0) {
        const u64* b2v = (const u64*)(sm + SM_B2);
#pragma unroll
        for (int q = 0; q < 32; q++) outp[q] = b2v[q];
    } else {
#pragma unroll
        for (int q = 0; q < 32; q++) outp[q] = 0ull;
    }
#pragma unroll
    for (int p = 0; p < 32; p++) {
        int kk = half * 64 + 2 * p;
        u64 z2 = acc[p];
        u64 zl = splat2(__uint_as_float((unsigned)z2));
        u64 zh = splat2(__uint_as_float((unsigned)(z2 >> 32)));
        const ulonglong2* r0 = (const ulonglong2*)(sm + SM_W2 + kk * 64);
        const ulonglong2* r1 = (const ulonglong2*)(sm + SM_W2 + (kk + 1) * 64);
#pragma unroll
        for (int q = 0; q < 16; q++) {
            ulonglong2 w0 = r0[q];
            ffma2(outp[2*q],   zl, w0.x);
            ffma2(outp[2*q+1], zl, w0.y);
        }
#pragma unroll
        for (int q = 0; q < 16; q++) {
            ulonglong2 w1 = r1[q];
            ffma2(outp[2*q],   zh, w1.x);
            ffma2(outp[2*q+1], zh, w1.y);
        }
    }

    // combine the two halves through smem (reuse W1 region)
    u64* P = (u64*)(sm + SM_W1);
    if (half == 1) {
#pragma unroll
        for (int q = 0; q < 32; q++) P[q * 128 + node] = outp[q];
    }
    __syncthreads();
    if (half == 0) {
#pragma unroll
        for (int q = 0; q < 32; q++) outp[q] = add2(outp[q], P[q * 128 + node]);

        float o[64];
        float ss = 0.f;
#pragma unroll
        for (int q = 0; q < 32; q++) {
            float lo = __uint_as_float((unsigned)outp[q]);
            float hi = __uint_as_float((unsigned)(outp[q] >> 32));
            o[2*q] = lo; o[2*q+1] = hi;
            ss = fmaf(lo, lo, ss);
            ss = fmaf(hi, hi, ss);
        }
        int gnode = base + node;
        if (gnode < N_NODES) {
            float sc = 1.f / fmaxf(sqrtf(ss), 1e-12f);
            float4* op = (float4*)(out + gnode * 64);
#pragma unroll
            for (int q = 0; q < 16; q++) {
                float4 v;
                v.x = o[4*q] * sc;   v.y = o[4*q+1] * sc;
                v.z = o[4*q+2] * sc; v.w = o[4*q+3] * sc;
                op[q] = v;
            }
        }
    }
}

// ---------------- launch ----------------
extern "C" void kernel_launch(void* const* d_in, const int* in_sizes, int n_in,
                              void* d_out, int out_size) {
    const float* x  = (const float*)d_in[0];
    const int*   ei = (const int*)  d_in[1];
    const float* kw = (const float*)d_in[2];
    const float* W0 = (const float*)d_in[3];
    const float* b0 = (const float*)d_in[4];
    const float* W1 = (const float*)d_in[5];
    const float* b1 = (const float*)d_in[6];
    const float* W2 = (const float*)d_in[7];
    const float* b2 = (const float*)d_in[8];
    float* out = (float*)d_out;
    const int* src = ei;
    const int* dst = ei + N_EDGES;

    cudaFuncSetAttribute(k_mlp1, cudaFuncAttributeMaxDynamicSharedMemorySize,
                         SM_TOTAL * (int)sizeof(float));

    k_init   <<<(N_NODES + 255) / 256, 256>>>();
    k_hist   <<<(N_EDGES + 255) / 256, 256>>>(dst);
    k_scan1  <<<(N_NODES + 1023) / 1024, 1024>>>();
    k_offsets<<<(N_NODES + 255) / 256, 256>>>();
    k_scatter<<<(N_EDGES + 255) / 256, 256>>>(src, dst, kw);
    k_conv0  <<<N_NODES / 8, 256>>>(x, W0, b0);
    k_conv1  <<<N_NODES / 8, 256>>>();
    k_mlp1   <<<(N_NODES + 127) / 128, 128 * 2, SM_TOTAL * (int)sizeof(float)>>>(W1, b1, W2, b2, out);
}

// round 4
// speedup vs baseline: 1.3688x; 1.3106x over previous
#include <cuda_runtime.h>
#include <math.h>

#define N_NODES 200000
#define N_EDGES 3200000

typedef unsigned long long u64;

// ---------------- static scratch ----------------
__device__ int    g_count [N_NODES];
__device__ int    g_rowptr[N_NODES];
__device__ int    g_cursor[N_NODES];
__device__ int    g_bsums [256];
__device__ float4 g_sedge [N_EDGES];     // {src(bits), kw0, kw1, pad}
__device__ float  g_h     [N_NODES * 32];
__device__ float  g_agg1  [N_NODES * 64];

// ---------------- packed f32x2 helpers ----------------
__device__ __forceinline__ u64 splat2(float x) {
    u64 r; unsigned xi = __float_as_uint(x);
    asm("mov.b64 %0, {%1, %1};" : "=l"(r) : "r"(xi));
    return r;
}
__device__ __forceinline__ void ffma2(u64& d, u64 a, u64 b) {
    asm("fma.rn.f32x2 %0, %1, %2, %0;" : "+l"(d) : "l"(a), "l"(b));
}
__device__ __forceinline__ u64 add2(u64 a, u64 b) {
    u64 r; asm("add.rn.f32x2 %0, %1, %2;" : "=l"(r) : "l"(a), "l"(b));
    return r;
}
__device__ __forceinline__ float lo32(u64 v) { return __uint_as_float((unsigned)v); }
__device__ __forceinline__ float hi32(u64 v) { return __uint_as_float((unsigned)(v >> 32)); }
__device__ __forceinline__ u64 pack2(float lo, float hi) {
    return ((u64)__float_as_uint(hi) << 32) | (u64)__float_as_uint(lo);
}

// ---------------- CSR build ----------------
__global__ void k_init() {
    int i = blockIdx.x * blockDim.x + threadIdx.x;
    if (i < N_NODES) g_count[i] = 0;
}

__global__ void k_hist(const int* __restrict__ dst) {
    int e = blockIdx.x * blockDim.x + threadIdx.x;
    if (e < N_EDGES) atomicAdd(&g_count[dst[e]], 1);
}

__global__ void k_scan1() {
    __shared__ int wsum[32];
    int tid = threadIdx.x;
    int i = blockIdx.x * 1024 + tid;
    int v = (i < N_NODES) ? g_count[i] : 0;
    int s = v;
#pragma unroll
    for (int o = 1; o < 32; o <<= 1) {
        int t = __shfl_up_sync(0xffffffffu, s, o);
        if ((tid & 31) >= o) s += t;
    }
    if ((tid & 31) == 31) wsum[tid >> 5] = s;
    __syncthreads();
    if (tid < 32) {
        int w = wsum[tid];
        int ws = w;
#pragma unroll
        for (int o = 1; o < 32; o <<= 1) {
            int t = __shfl_up_sync(0xffffffffu, ws, o);
            if (tid >= o) ws += t;
        }
        wsum[tid] = ws - w;
    }
    __syncthreads();
    int excl = s - v + wsum[tid >> 5];
    if (i < N_NODES) g_rowptr[i] = excl;
    if (tid == 1023) g_bsums[blockIdx.x] = excl + v;
}

__global__ void k_offsets() {
    __shared__ int soff;
    int g = blockIdx.x >> 2;
    int tid = threadIdx.x;
    if (tid < 32) {
        int acc = 0;
        for (int j = tid; j < g; j += 32) acc += g_bsums[j];
#pragma unroll
        for (int o = 16; o; o >>= 1) acc += __shfl_xor_sync(0xffffffffu, acc, o);
        if (tid == 0) soff = acc;
    }
    __syncthreads();
    int i = blockIdx.x * 256 + tid;
    if (i < N_NODES) {
        int v = g_rowptr[i] + soff;
        g_rowptr[i] = v;
        g_cursor[i] = v;
    }
}

__global__ void k_scatter(const int* __restrict__ src, const int* __restrict__ dst,
                          const float* __restrict__ kw) {
    int e = blockIdx.x * blockDim.x + threadIdx.x;
    if (e < N_EDGES) {
        int t = dst[e];
        int p = atomicAdd(&g_cursor[t], 1);
        float4 v;
        v.x = __int_as_float(src[e]);
        v.y = kw[e];
        v.z = kw[N_EDGES + e];
        v.w = 0.f;
        g_sedge[p] = v;
    }
}

// ---------------- fused conv0 + mlp0 + L2norm: warp per node ----------------
__global__ void k_conv0(const float* __restrict__ x,
                        const float* __restrict__ W0, const float* __restrict__ b0) {
    __shared__ float W0s[512];
    __shared__ float b0s[32];
    int tid = threadIdx.x;
    W0s[tid] = W0[tid];
    W0s[tid + 256] = W0[tid + 256];
    if (tid < 32) b0s[tid] = b0[tid];
    __syncthreads();

    int warp = tid >> 5, lane = tid & 31;
    int node = blockIdx.x * 8 + warp;
    int f = lane & 7, sub = lane >> 3;
    int start = g_rowptr[node], end = start + g_count[node];
    float a0 = 0.f, a1 = 0.f;
    int e = start;
    for (; e + 4 <= end; e += 4) {
        float4 E = g_sedge[e + sub];
        int s = __float_as_int(E.x);
        float v = __ldg(&x[s * 8 + f]);
        a0 = fmaf(E.y, v, a0);
        a1 = fmaf(E.z, v, a1);
    }
    if (e + sub < end) {
        float4 E = g_sedge[e + sub];
        int s = __float_as_int(E.x);
        float v = __ldg(&x[s * 8 + f]);
        a0 = fmaf(E.y, v, a0);
        a1 = fmaf(E.z, v, a1);
    }
    a0 += __shfl_xor_sync(0xffffffffu, a0, 8);
    a0 += __shfl_xor_sync(0xffffffffu, a0, 16);
    a1 += __shfl_xor_sync(0xffffffffu, a1, 8);
    a1 += __shfl_xor_sync(0xffffffffu, a1, 16);

    float val = (lane & 8) ? a1 : a0;
    float acc = b0s[lane];
#pragma unroll
    for (int k = 0; k < 16; k++) {
        float ak = __shfl_sync(0xffffffffu, val, k);
        acc = fmaf(ak, W0s[k * 32 + lane], acc);
    }
    float ss = acc * acc;
#pragma unroll
    for (int o = 16; o; o >>= 1) ss += __shfl_xor_sync(0xffffffffu, ss, o);
    float sc = 1.f / fmaxf(sqrtf(ss), 1e-12f);
    g_h[node * 32 + lane] = acc * sc;
}

// ---------------- layer 1 conv: warp per node, lane = feature ----------------
__global__ void k_conv1() {
    int warp = threadIdx.x >> 5, lane = threadIdx.x & 31;
    int node = blockIdx.x * 8 + warp;
    int start = g_rowptr[node], end = start + g_count[node];
    float a0 = 0.f, a1 = 0.f;
    const float* __restrict__ h = g_h;
    int e = start;
    for (; e + 4 <= end; e += 4) {
        float4 E0 = g_sedge[e], E1 = g_sedge[e+1], E2 = g_sedge[e+2], E3 = g_sedge[e+3];
        float v0 = h[__float_as_int(E0.x) * 32 + lane];
        float v1 = h[__float_as_int(E1.x) * 32 + lane];
        float v2 = h[__float_as_int(E2.x) * 32 + lane];
        float v3 = h[__float_as_int(E3.x) * 32 + lane];
        a0 = fmaf(E0.y, v0, a0); a0 = fmaf(E1.y, v1, a0);
        a0 = fmaf(E2.y, v2, a0); a0 = fmaf(E3.y, v3, a0);
        a1 = fmaf(E0.z, v0, a1); a1 = fmaf(E1.z, v1, a1);
        a1 = fmaf(E2.z, v2, a1); a1 = fmaf(E3.z, v3, a1);
    }
    for (; e < end; ++e) {
        float4 E = g_sedge[e];
        float v = h[__float_as_int(E.x) * 32 + lane];
        a0 = fmaf(E.y, v, a0);
        a1 = fmaf(E.z, v, a1);
    }
    g_agg1[node*64 + lane]      = a0;
    g_agg1[node*64 + 32 + lane] = a1;
}

// ---------------- layer 1 MLP: register-tiled SGEMM, 8x8 tile/thread ----------------
// smem layout (floats):
//   R region [0, 16896): W1 at [0,8192) rows stride 128; A_T at [8192 + k*132 + node]
//                        after mm1, Z overwrites R: row k at [k*132), 32 chunks of 16B,
//                        chunk rotated by (h>>3)
//   W2 at [16896, 25088): rows stride 64
//   b1 at [25088,25216), b2 at [25216,25280)
#define SM_W1 0
#define SM_A  8192
#define SM_W2 16896
#define SM_B1 25088
#define SM_B2 25216
#define SM_TOTAL 25280

__global__ void __launch_bounds__(256, 2)
k_mlp1(const float* __restrict__ W1, const float* __restrict__ b1,
       const float* __restrict__ W2, const float* __restrict__ b2,
       float* __restrict__ out) {
    extern __shared__ float sm[];
    int tid = threadIdx.x;
    int th = tid & 15;        // hidden-tile index (fast within warp)
    int tn = tid >> 4;        // node-tile index: nodes tn*8 .. +8

    for (int i = tid; i < 8192; i += 256) {
        sm[SM_W1 + i] = W1[i];
        sm[SM_W2 + i] = W2[i];
    }
    if (tid < 128) sm[SM_B1 + tid] = b1[tid];
    if (tid < 64)  sm[SM_B2 + tid] = b2[tid];

    int base = blockIdx.x * 128;
    // stage A transposed: A_T[k][node], stride 132 (16B-aligned rows)
    for (int idx = tid; idx < 8192; idx += 256) {
        int g = base * 64 + idx;
        float v = (g < N_NODES * 64) ? g_agg1[g] : 0.f;
        sm[SM_A + (idx & 63) * 132 + (idx >> 6)] = v;
    }
    __syncthreads();

    // ---- mm1: C1[128 nodes][128 hid] = A[128][64] @ W1 + b1 ----
    // acc[i*4+np]: hid h = th*8+i, node pair (tn*8+2np, +1)
    u64 acc[32];
#pragma unroll
    for (int i = 0; i < 8; i++) {
        u64 bi = splat2(sm[SM_B1 + th * 8 + i]);
#pragma unroll
        for (int np = 0; np < 4; np++) acc[i * 4 + np] = bi;
    }
    {
        const float* At  = sm + SM_A + tn * 8;
        const float* W1r = sm + SM_W1 + th * 8;
#pragma unroll 4
        for (int k = 0; k < 64; k++) {
            ulonglong2 avA = *(const ulonglong2*)(At + k * 132);
            ulonglong2 avB = *(const ulonglong2*)(At + k * 132 + 4);
            u64 A2[4] = {avA.x, avA.y, avB.x, avB.y};
            float4 w0 = *(const float4*)(W1r + k * 128);
            float4 w1 = *(const float4*)(W1r + k * 128 + 4);
            u64 ws[8] = {splat2(w0.x), splat2(w0.y), splat2(w0.z), splat2(w0.w),
                         splat2(w1.x), splat2(w1.y), splat2(w1.z), splat2(w1.w)};
#pragma unroll
            for (int i = 0; i < 8; i++)
#pragma unroll
                for (int np = 0; np < 4; np++)
                    ffma2(acc[i * 4 + np], A2[np], ws[i]);
        }
    }
    __syncthreads();   // all mm1 reads of W1/A done; R becomes Z

    // relu + store Z k-major with 16B-chunk rotation: q' = (q + (h>>3)) & 31
    {
        float* Zs = sm;
#pragma unroll
        for (int i = 0; i < 8; i++) {
            int h = th * 8 + i;
            int rot = h >> 3;   // == th
            float* row = Zs + h * 132;
#pragma unroll
            for (int np = 0; np < 4; np++) {
                u64 v = acc[i * 4 + np];
                u64 r = pack2(fmaxf(lo32(v), 0.f), fmaxf(hi32(v), 0.f));
                int q  = 2 * tn + (np >> 1);          // 16B chunk of this node-pair
                int qp = (q + rot) & 31;
                *(u64*)(row + qp * 4 + (np & 1) * 2) = r;
            }
        }
    }
    __syncthreads();

    // ---- mm2: O[128 nodes][64] = Z[128][128] @ W2 + b2 ----
    // acc2[o*4+np]: out col = th*4+o, node pair (tn*8+2np, +1)
    u64 acc2[16];
#pragma unroll
    for (int o = 0; o < 4; o++) {
        u64 bo = splat2(sm[SM_B2 + th * 4 + o]);
#pragma unroll
        for (int np = 0; np < 4; np++) acc2[o * 4 + np] = bo;
    }
    {
        const float* Zs  = sm;
        const float* W2r = sm + SM_W2 + th * 4;
#pragma unroll 4
        for (int k = 0; k < 128; k++) {
            int rot = k >> 3;
            const float* row = Zs + k * 132;
            ulonglong2 z0 = *(const ulonglong2*)(row + (((2 * tn + 0 + rot) & 31) << 2));
            ulonglong2 z1 = *(const ulonglong2*)(row + (((2 * tn + 1 + rot) & 31) << 2));
            u64 A2[4] = {z0.x, z0.y, z1.x, z1.y};
            float4 wv = *(const float4*)(W2r + k * 64);
            u64 ws[4] = {splat2(wv.x), splat2(wv.y), splat2(wv.z), splat2(wv.w)};
#pragma unroll
            for (int o = 0; o < 4; o++)
#pragma unroll
                for (int np = 0; np < 4; np++)
                    ffma2(acc2[o * 4 + np], A2[np], ws[o]);
        }
    }

    // ---- L2 norm (reduce across the 16 th-lanes) + store ----
    u64 ss2[4];
#pragma unroll
    for (int np = 0; np < 4; np++) ss2[np] = 0ull;
#pragma unroll
    for (int o = 0; o < 4; o++)
#pragma unroll
        for (int np = 0; np < 4; np++)
            ffma2(ss2[np], acc2[o * 4 + np], acc2[o * 4 + np]);
#pragma unroll
    for (int m = 1; m < 16; m <<= 1)
#pragma unroll
        for (int np = 0; np < 4; np++)
            ss2[np] = add2(ss2[np], __shfl_xor_sync(0xffffffffu, ss2[np], m));

#pragma unroll
    for (int np = 0; np < 4; np++) {
        float se = 1.f / fmaxf(sqrtf(lo32(ss2[np])), 1e-12f);
        float so = 1.f / fmaxf(sqrtf(hi32(ss2[np])), 1e-12f);
        int ne = base + tn * 8 + 2 * np;
        if (ne < N_NODES) {
            float4 v;
            v.x = lo32(acc2[0 * 4 + np]) * se;
            v.y = lo32(acc2[1 * 4 + np]) * se;
            v.z = lo32(acc2[2 * 4 + np]) * se;
            v.w = lo32(acc2[3 * 4 + np]) * se;
            *(float4*)(out + ne * 64 + th * 4) = v;
        }
        if (ne + 1 < N_NODES) {
            float4 v;
            v.x = hi32(acc2[0 * 4 + np]) * so;
            v.y = hi32(acc2[1 * 4 + np]) * so;
            v.z = hi32(acc2[2 * 4 + np]) * so;
            v.w = hi32(acc2[3 * 4 + np]) * so;
            *(float4*)(out + (ne + 1) * 64 + th * 4) = v;
        }
    }
}

// ---------------- launch ----------------
extern "C" void kernel_launch(void* const* d_in, const int* in_sizes, int n_in,
                              void* d_out, int out_size) {
    const float* x  = (const float*)d_in[0];
    const int*   ei = (const int*)  d_in[1];
    const float* kw = (const float*)d_in[2];
    const float* W0 = (const float*)d_in[3];
    const float* b0 = (const float*)d_in[4];
    const float* W1 = (const float*)d_in[5];
    const float* b1 = (const float*)d_in[6];
    const float* W2 = (const float*)d_in[7];
    const float* b2 = (const float*)d_in[8];
    float* out = (float*)d_out;
    const int* src = ei;
    const int* dst = ei + N_EDGES;

    cudaFuncSetAttribute(k_mlp1, cudaFuncAttributeMaxDynamicSharedMemorySize,
                         SM_TOTAL * (int)sizeof(float));

    k_init   <<<(N_NODES + 255) / 256, 256>>>();
    k_hist   <<<(N_EDGES + 255) / 256, 256>>>(dst);
    k_scan1  <<<(N_NODES + 1023) / 1024, 1024>>>();
    k_offsets<<<(N_NODES + 255) / 256, 256>>>();
    k_scatter<<<(N_EDGES + 255) / 256, 256>>>(src, dst, kw);
    k_conv0  <<<N_NODES / 8, 256>>>(x, W0, b0);
    k_conv1  <<<N_NODES / 8, 256>>>();
    k_mlp1   <<<(N_NODES + 127) / 128, 256, SM_TOTAL * (int)sizeof(float)>>>(W1, b1, W2, b2, out);
}